// round 6
// baseline (speedup 1.0000x reference)
#include <cuda_runtime.h>
#include <cstdint>

#define NB      96
#define MTILE   32
#define THREADS 128

// W2 transposed: W2I[i*256 + j] = W2[j*256 + i]
__device__ float W2I[256 * 256];

// ---- packed f32x2 helpers (sm_103a) ----
__device__ __forceinline__ unsigned long long pack2(float x, float y) {
    unsigned long long r;
    asm("mov.b64 %0, {%1, %2};" : "=l"(r) : "f"(x), "f"(y));
    return r;
}
__device__ __forceinline__ void unpack2(unsigned long long v, float& x, float& y) {
    asm("mov.b64 {%0, %1}, %2;" : "=f"(x), "=f"(y) : "l"(v));
}
__device__ __forceinline__ void ffma2(unsigned long long& d, unsigned long long a, unsigned long long b) {
    asm("fma.rn.f32x2 %0, %1, %2, %0;" : "+l"(d) : "l"(a), "l"(b));
}

__global__ void transpose_kernel(const float* __restrict__ W2) {
    int j = blockIdx.x;     // original row
    int i = threadIdx.x;    // original col (coalesced read)
    W2I[i * 256 + j] = W2[j * 256 + i];
}

__global__ __launch_bounds__(THREADS, 2)
void net_kernel(const float* __restrict__ X,      // [8192][96][4]
                const float* __restrict__ TN,     // [8192][96]
                const float* __restrict__ DN,     // [8192][96]
                const float* __restrict__ A0,     // [8192]
                const float* __restrict__ S0,     // [8192]
                const float* __restrict__ LAM,
                const float* __restrict__ BUD,
                const float* __restrict__ W1,     // [256][6]
                const float* __restrict__ B1,     // [256]
                const float* __restrict__ B2,     // [256]
                const float* __restrict__ W3,     // [256]
                const float* __restrict__ B3,     // [1]
                float* __restrict__ OUT)          // [8192][96]
{
    __shared__ __align__(16) float h1s[256 * MTILE];   // [i][m], 32 KB
    __shared__ __align__(8)  float W1T[6 * 256];       // [c][k]
    __shared__ __align__(8)  float B1s[256];
    __shared__ __align__(16) float RED[4 * MTILE];
    __shared__ float acS[MTILE], stS[MTILE], bgS[MTILE],
                     cuS[MTILE], adS[MTILE], ssS[MTILE];

    const int tid  = threadIdx.x;
    const int lane = tid & 31;
    const int w    = tid >> 5;
    const int jg   = lane >> 2;          // 0..7
    const int mg   = lane & 3;           // 0..3
    const int jbase = w * 64 + jg * 8;   // 8 output rows per lane
    const int mbase = mg * 8;            // 8 batch per lane
    const int base = blockIdx.x * MTILE;

    // stage small weights (W1 transposed to [c][k] so k-pairs are contiguous)
    for (int idx = tid; idx < 6 * 256; idx += THREADS) {
        int c = idx >> 8, k = idx & 255;
        W1T[c * 256 + k] = W1[k * 6 + c];
    }
    for (int idx = tid; idx < 256; idx += THREADS) B1s[idx] = B1[idx];

    float b2r[8], w3r[8];
    #pragma unroll
    for (int j = 0; j < 8; j++) { b2r[j] = B2[jbase + j]; w3r[j] = W3[jbase + j]; }
    const float b3v = B3[0];
    const float lam = LAM[0], bud = BUD[0];
    const float budH     = __fdiv_rn(bud, 96.0f);
    const float per_step = lam * 2.0f + budH;

    if (tid < MTILE) {
        acS[tid] = A0[base + tid];
        stS[tid] = S0[base + tid];
        bgS[tid] = per_step;
        cuS[tid] = 0.0f; adS[tid] = 0.0f; ssS[tid] = 0.0f;
    }
    __syncthreads();

    // layer-1 assignment: thread owns batch column m1 and 32 k-pairs
    const int m1  = tid & 31;
    const int kp0 = (tid >> 5) * 32;     // pair index start (k = 2*pair)
    const float4* xrow = reinterpret_cast<const float4*>(X + (size_t)(base + m1) * (NB * 4));

    const float4* wp4 = reinterpret_cast<const float4*>(W2I) + (jbase >> 2);

    for (int t = 0; t < NB; t++) {
        // ---- layer 1: h1s[k][m1] = relu(W1[k].x + b1[k]), k-pairs packed ----
        {
            float4 xv = xrow[t];
            unsigned long long xp[6];
            xp[0] = pack2(xv.x, xv.x);
            xp[1] = pack2(xv.y, xv.y);
            xp[2] = pack2(xv.z, xv.z);
            xp[3] = pack2(xv.w, xv.w);
            float a4 = acS[m1], s5 = stS[m1];
            xp[4] = pack2(a4, a4);
            xp[5] = pack2(s5, s5);
            #pragma unroll 4
            for (int kp = 0; kp < 32; kp++) {
                int k = 2 * (kp0 + kp);
                unsigned long long s = *reinterpret_cast<const unsigned long long*>(&B1s[k]);
                #pragma unroll
                for (int c = 0; c < 6; c++)
                    ffma2(s, *reinterpret_cast<const unsigned long long*>(&W1T[c * 256 + k]), xp[c]);
                float s0, s1;
                unpack2(s, s0, s1);
                h1s[k * MTILE + m1]       = fmaxf(s0, 0.0f);
                h1s[(k + 1) * MTILE + m1] = fmaxf(s1, 0.0f);
            }
        }
        __syncthreads();

        // ---- layer 2: 8 j-rows x 8 m per lane, packed f32x2 ----
        unsigned long long acc[32];
        #pragma unroll
        for (int j = 0; j < 8; j++) {
            unsigned long long bp = pack2(b2r[j], b2r[j]);
            acc[j * 4 + 0] = bp; acc[j * 4 + 1] = bp;
            acc[j * 4 + 2] = bp; acc[j * 4 + 3] = bp;
        }
        #pragma unroll 2
        for (int i = 0; i < 256; i++) {
            float4 wv0 = wp4[i * 64];
            float4 wv1 = wp4[i * 64 + 1];
            ulonglong2 ha = *reinterpret_cast<const ulonglong2*>(&h1s[i * MTILE + mbase]);
            ulonglong2 hb = *reinterpret_cast<const ulonglong2*>(&h1s[i * MTILE + mbase + 4]);
            #pragma unroll
            for (int j = 0; j < 4; j++) {
                const float wj = (&wv0.x)[j];
                unsigned long long wpk = pack2(wj, wj);
                ffma2(acc[j * 4 + 0], wpk, ha.x);
                ffma2(acc[j * 4 + 1], wpk, ha.y);
                ffma2(acc[j * 4 + 2], wpk, hb.x);
                ffma2(acc[j * 4 + 3], wpk, hb.y);
            }
            #pragma unroll
            for (int j = 4; j < 8; j++) {
                const float wj = (&wv1.x)[j - 4];
                unsigned long long wpk = pack2(wj, wj);
                ffma2(acc[j * 4 + 0], wpk, ha.x);
                ffma2(acc[j * 4 + 1], wpk, ha.y);
                ffma2(acc[j * 4 + 2], wpk, hb.x);
                ffma2(acc[j * 4 + 3], wpk, hb.y);
            }
        }

        // ---- layer 3 partials: per lane, 8 m sums over its 8 j ----
        float cm[8];
        #pragma unroll
        for (int q = 0; q < 8; q++) cm[q] = 0.0f;
        #pragma unroll
        for (int j = 0; j < 8; j++) {
            #pragma unroll
            for (int p = 0; p < 4; p++) {
                float v0, v1;
                unpack2(acc[j * 4 + p], v0, v1);
                cm[2 * p]     = fmaf(w3r[j], fmaxf(v0, 0.0f), cm[2 * p]);
                cm[2 * p + 1] = fmaf(w3r[j], fmaxf(v1, 0.0f), cm[2 * p + 1]);
            }
        }
        // reduce over jg (lane bits 2,3,4)
        #pragma unroll
        for (int off = 4; off <= 16; off <<= 1) {
            #pragma unroll
            for (int q = 0; q < 8; q++)
                cm[q] += __shfl_xor_sync(0xFFFFFFFFu, cm[q], off);
        }
        if (jg == 0) {
            *reinterpret_cast<float4*>(&RED[w * 32 + mbase]) =
                make_float4(cm[0], cm[1], cm[2], cm[3]);
            *reinterpret_cast<float4*>(&RED[w * 32 + mbase + 4]) =
                make_float4(cm[4], cm[5], cm[6], cm[7]);
        }
        __syncthreads();

        // ---- scalar recurrence: one thread per batch element ----
        if (tid < MTILE) {
            const int m = tid;
            float a_ml = RED[m] + RED[32 + m] + RED[64 + m] + RED[96 + m] + b3v;
            a_ml = fmaxf(a_ml, 0.0f);

            float state_ = stS[m];
            float demand = X[(size_t)(base + m) * (NB * 4) + t * 4];
            float a_prior = fminf(__fdiv_rn(fmaxf(state_ + demand, 0.0f), 0.8f), 10.0f);

            int n = 95 - t;
            float p = (n <= 63) ? __uint_as_float((unsigned)(127 - 2 * n) << 23) : 0.0f;
            float Gamma = 2.0f + 0.5f * (1.0f - p);

            float bgt = bgS[m];
            float sgn = (a_ml < a_prior) ? 1.0f : -1.0f;
            float a_out = a_ml +
                fmaxf(fabsf(a_ml - a_prior) - __fdiv_rn(bgt, Gamma), 0.0f) * sgn;

            float noise  = TN[(size_t)(base + m) * NB + t];
            float noise2 = DN[(size_t)(base + m) * NB + t];
            float ns = fminf(fmaxf(state_ * (1.0f - noise2) + demand
                                   - (0.8f + noise) * a_out, 0.0f), 15.0f);
            float c_cost = 0.1f * ns * ns + ns + 2.0f;

            float ad_new = fabsf(a_out - a_prior);
            float Sold = ssS[m];
            float Snew = 0.25f * Sold + ad_new;
            float cum_d = 2.0f * ad_new + 0.375f * Sold;
            float c_prior = fmaxf(2.0f, c_cost - cum_d);
            float cum_c = cuS[m];
            float cum_c_new = cum_c + (1.0f + lam) * c_prior - c_cost;
            float cum_d_g = 0.5f * Snew * (1.0f - p);

            float bgt_if = fmaxf(fmaxf(bgt + per_step - ad_new * Gamma, 0.0f),
                                 cum_c_new - cum_d_g + lam * 2.0f + budH * (float)(t + 2));
            float bgt_else = fmaxf(bgt + per_step - adS[m] * Gamma, 0.0f);

            bool last = (t == NB - 1);
            bgS[m] = last ? bgt_else : bgt_if;
            cuS[m] = last ? cum_c : cum_c_new;
            adS[m] = ad_new;
            acS[m] = a_out;
            stS[m] = ns;
            ssS[m] = Snew;
            OUT[(size_t)(base + m) * NB + t] = a_out;
        }
        __syncthreads();
    }
}

extern "C" void kernel_launch(void* const* d_in, const int* in_sizes, int n_in,
                              void* d_out, int out_size) {
    (void)in_sizes; (void)n_in; (void)out_size;
    transpose_kernel<<<256, 256>>>((const float*)d_in[9]);   // W2
    net_kernel<<<8192 / MTILE, THREADS>>>(
        (const float*)d_in[0],   // policy_in_c
        (const float*)d_in[1],   // trans_noise
        (const float*)d_in[2],   // demand_noise
        (const float*)d_in[3],   // action_pre
        (const float*)d_in[4],   // state_pre
        (const float*)d_in[5],   // Lambda
        (const float*)d_in[6],   // Budget
        (const float*)d_in[7],   // W1
        (const float*)d_in[8],   // b1
        (const float*)d_in[10],  // b2
        (const float*)d_in[11],  // W3
        (const float*)d_in[12],  // b3
        (float*)d_out);
}

// round 7
// speedup vs baseline: 1.8289x; 1.8289x over previous
#include <cuda_runtime.h>
#include <cstdint>

#define NB      96
#define MTILE   16
#define THREADS 128

// W2 transposed: W2I[i*256 + j] = W2[j*256 + i]
__device__ float W2I[256 * 256];

// ---- packed f32x2 helpers (sm_103a) ----
__device__ __forceinline__ unsigned long long pack2(float x, float y) {
    unsigned long long r;
    asm("mov.b64 %0, {%1, %2};" : "=l"(r) : "f"(x), "f"(y));
    return r;
}
__device__ __forceinline__ void unpack2(unsigned long long v, float& x, float& y) {
    asm("mov.b64 {%0, %1}, %2;" : "=f"(x), "=f"(y) : "l"(v));
}
__device__ __forceinline__ void ffma2(unsigned long long& d, unsigned long long a, unsigned long long b) {
    asm("fma.rn.f32x2 %0, %1, %2, %0;" : "+l"(d) : "l"(a), "l"(b));
}

__global__ void transpose_kernel(const float* __restrict__ W2) {
    int j = blockIdx.x;
    int i = threadIdx.x;
    W2I[i * 256 + j] = W2[j * 256 + i];
}

__global__ __launch_bounds__(THREADS, 4)
void net_kernel(const float* __restrict__ X,      // [8192][96][4]
                const float* __restrict__ TN,     // [8192][96]
                const float* __restrict__ DN,     // [8192][96]
                const float* __restrict__ A0,     // [8192]
                const float* __restrict__ S0,     // [8192]
                const float* __restrict__ LAM,
                const float* __restrict__ BUD,
                const float* __restrict__ W1,     // [256][6]
                const float* __restrict__ B1,     // [256]
                const float* __restrict__ B2,     // [256]
                const float* __restrict__ W3,     // [256]
                const float* __restrict__ B3,     // [1]
                float* __restrict__ OUT)          // [8192][96]
{
    __shared__ __align__(16) float h1s[256 * MTILE];   // [j][m], 16 KB
    __shared__ __align__(8)  float W1J[6 * 256];       // [c][jpair] f32x2-over-j
    __shared__ __align__(8)  float B1J[256];           // bias, j-pair order
    __shared__ float red[4][MTILE];
    __shared__ float outS[MTILE][NB];                  // 6 KB
    __shared__ float actS[MTILE], stS[MTILE], bgtS[MTILE],
                     cumcS[MTILE], adpS[MTILE], SS[MTILE];

    const int k    = threadIdx.x;      // 0..127
    const int lane = k & 31;
    const int warp = k >> 5;
    const int jg   = lane >> 1;        // 0..15
    const int mg   = lane & 1;         // 0..1
    const int m_h1 = k & 15;           // layer-1: batch slot
    const int r_h1 = k >> 4;           // layer-1: pair-group 0..7
    const int base = blockIdx.x * MTILE;
    const int jbase = warp * 64 + jg * 4;

    // stage W1 in j-pair-packed layout: W1J[c*256 + 2*kp + {0,1}] = W1[2kp+{0,1}][c]
    for (int idx = k; idx < 6 * 256; idx += THREADS) {
        int c = idx >> 8, j = idx & 255;
        W1J[c * 256 + j] = W1[j * 6 + c];
    }
    for (int idx = k; idx < 256; idx += THREADS) B1J[idx] = B1[idx];

    float b2r[4], w3r[4];
    #pragma unroll
    for (int j = 0; j < 4; j++) { b2r[j] = B2[jbase + j]; w3r[j] = W3[jbase + j]; }
    const float b3v = B3[0];
    const float lam = LAM[0], bud = BUD[0];
    const float budH     = __fdiv_rn(bud, 96.0f);
    const float per_step = lam * 2.0f + budH;

    if (k < MTILE) {
        actS[k]  = A0[base + k];
        stS[k]   = S0[base + k];
        bgtS[k]  = per_step;
        cumcS[k] = 0.0f;
        adpS[k]  = 0.0f;
        SS[k]    = 0.0f;
    }
    __syncthreads();

    const char* hC = reinterpret_cast<const char*>(h1s) + mg * 32;
    const float4* w2a4 = reinterpret_cast<const float4*>(W2I) + (jbase >> 2);
    const float4* xrow = reinterpret_cast<const float4*>(X + (size_t)(base + m_h1) * (NB * 4));

    for (int t = 0; t < NB; t++) {
        // ---- layer 1: thread (m_h1, r_h1) computes 16 j-pairs for its m ----
        {
            float4 xv = xrow[t];                 // 8 threads/m dedupe in L1
            unsigned long long xp[6];
            xp[0] = pack2(xv.x, xv.x);
            xp[1] = pack2(xv.y, xv.y);
            xp[2] = pack2(xv.z, xv.z);
            xp[3] = pack2(xv.w, xv.w);
            float a4 = actS[m_h1], s5 = stS[m_h1];
            xp[4] = pack2(a4, a4);
            xp[5] = pack2(s5, s5);
            #pragma unroll 4
            for (int i = 0; i < 16; i++) {
                int j = 2 * r_h1 + (i << 4);     // even j of this pair
                unsigned long long s = *reinterpret_cast<const unsigned long long*>(&B1J[j]);
                #pragma unroll
                for (int c = 0; c < 6; c++)
                    ffma2(s, *reinterpret_cast<const unsigned long long*>(&W1J[c * 256 + j]), xp[c]);
                float s0, s1;
                unpack2(s, s0, s1);
                h1s[j * MTILE + m_h1]       = fmaxf(s0, 0.0f);
                h1s[(j + 1) * MTILE + m_h1] = fmaxf(s1, 0.0f);
            }
        }
        __syncthreads();

        // ---- layer 2: 4 j-rows x 8 m per lane, packed f32x2 (R3 verbatim) ----
        unsigned long long acc[16];
        #pragma unroll
        for (int j = 0; j < 4; j++) {
            unsigned long long bp = pack2(b2r[j], b2r[j]);
            acc[j * 4 + 0] = bp; acc[j * 4 + 1] = bp;
            acc[j * 4 + 2] = bp; acc[j * 4 + 3] = bp;
        }
        #pragma unroll 4
        for (int i = 0; i < 256; i++) {
            float4 wv = w2a4[i * 64];
            ulonglong2 ha = *reinterpret_cast<const ulonglong2*>(hC + i * 64);
            ulonglong2 hb = *reinterpret_cast<const ulonglong2*>(hC + i * 64 + 16);
            #pragma unroll
            for (int j = 0; j < 4; j++) {
                const float wj = (&wv.x)[j];
                unsigned long long wpk = pack2(wj, wj);
                ffma2(acc[j * 4 + 0], wpk, ha.x);
                ffma2(acc[j * 4 + 1], wpk, ha.y);
                ffma2(acc[j * 4 + 2], wpk, hb.x);
                ffma2(acc[j * 4 + 3], wpk, hb.y);
            }
        }

        // ---- layer 3 partials ----
        float cm[8];
        #pragma unroll
        for (int q = 0; q < 8; q++) cm[q] = 0.0f;
        #pragma unroll
        for (int j = 0; j < 4; j++) {
            #pragma unroll
            for (int p = 0; p < 4; p++) {
                float v0, v1;
                unpack2(acc[j * 4 + p], v0, v1);
                cm[2 * p]     = fmaf(w3r[j], fmaxf(v0, 0.0f), cm[2 * p]);
                cm[2 * p + 1] = fmaf(w3r[j], fmaxf(v1, 0.0f), cm[2 * p + 1]);
            }
        }
        #pragma unroll
        for (int off = 2; off <= 16; off <<= 1) {
            #pragma unroll
            for (int q = 0; q < 8; q++)
                cm[q] += __shfl_xor_sync(0xFFFFFFFFu, cm[q], off);
        }
        if (jg == 0) {
            #pragma unroll
            for (int q = 0; q < 8; q++) red[warp][mg * 8 + q] = cm[q];
        }
        __syncthreads();

        // ---- scalar recurrence ----
        if (k < MTILE) {
            const int m = k;
            float a_ml = red[0][m] + red[1][m] + red[2][m] + red[3][m] + b3v;
            a_ml = fmaxf(a_ml, 0.0f);

            float state_ = stS[m];
            float demand = X[(size_t)(base + m) * (NB * 4) + t * 4];  // L1 hit
            float a_prior = fminf(__fdiv_rn(fmaxf(state_ + demand, 0.0f), 0.8f), 10.0f);

            int n = 95 - t;
            float p = (n <= 63) ? __uint_as_float((unsigned)(127 - 2 * n) << 23) : 0.0f;
            float Gamma = 2.0f + 0.5f * (1.0f - p);

            float bgt = bgtS[m];
            float sgn = (a_ml < a_prior) ? 1.0f : -1.0f;
            float a_out = a_ml +
                fmaxf(fabsf(a_ml - a_prior) - __fdiv_rn(bgt, Gamma), 0.0f) * sgn;

            float noise  = TN[(size_t)(base + m) * NB + t];
            float noise2 = DN[(size_t)(base + m) * NB + t];
            float ns = fminf(fmaxf(state_ * (1.0f - noise2) + demand
                                   - (0.8f + noise) * a_out, 0.0f), 15.0f);
            float c_cost = 0.1f * ns * ns + ns + 2.0f;

            float ad_new = fabsf(a_out - a_prior);
            float Sold = SS[m];
            float Snew = 0.25f * Sold + ad_new;
            float cum_d = 2.0f * ad_new + 0.375f * Sold;
            float c_prior = fmaxf(2.0f, c_cost - cum_d);
            float cum_c = cumcS[m];
            float cum_c_new = cum_c + (1.0f + lam) * c_prior - c_cost;
            float cum_d_g = 0.5f * Snew * (1.0f - p);

            float bgt_if = fmaxf(fmaxf(bgt + per_step - ad_new * Gamma, 0.0f),
                                 cum_c_new - cum_d_g + lam * 2.0f + budH * (float)(t + 2));
            float bgt_else = fmaxf(bgt + per_step - adpS[m] * Gamma, 0.0f);

            bool last = (t == NB - 1);
            bgtS[m]  = last ? bgt_else : bgt_if;
            cumcS[m] = last ? cum_c : cum_c_new;
            adpS[m]  = ad_new;
            actS[m]  = a_out;
            stS[m]   = ns;
            SS[m]    = Snew;
            outS[m][t] = a_out;
        }
        __syncthreads();
    }

    // ---- coalesced output flush ----
    for (int idx = k; idx < MTILE * NB; idx += THREADS) {
        int m = idx / NB, t = idx - m * NB;
        OUT[(size_t)(base + m) * NB + t] = outS[m][t];
    }
}

extern "C" void kernel_launch(void* const* d_in, const int* in_sizes, int n_in,
                              void* d_out, int out_size) {
    (void)in_sizes; (void)n_in; (void)out_size;
    transpose_kernel<<<256, 256>>>((const float*)d_in[9]);   // W2
    net_kernel<<<8192 / MTILE, THREADS>>>(
        (const float*)d_in[0],   // policy_in_c
        (const float*)d_in[1],   // trans_noise
        (const float*)d_in[2],   // demand_noise
        (const float*)d_in[3],   // action_pre
        (const float*)d_in[4],   // state_pre
        (const float*)d_in[5],   // Lambda
        (const float*)d_in[6],   // Budget
        (const float*)d_in[7],   // W1
        (const float*)d_in[8],   // b1
        (const float*)d_in[10],  // b2
        (const float*)d_in[11],  // W3
        (const float*)d_in[12],  // b3
        (float*)d_out);
}

// round 8
// speedup vs baseline: 5.4668x; 2.9891x over previous
#include <cuda_runtime.h>
#include <cstdint>

#define NB      96
#define MT      64
#define THREADS 256
#define NCTA    128

typedef unsigned long long ull;

// W2 fragments, fragment-linear: [J(16)][KT(16)][lane(32)] x uint4(a0..a3)
__device__ uint4 WFhi4[16 * 16 * 32];
__device__ uint4 WFlo4[16 * 16 * 32];

// ---- helpers ----
__device__ __forceinline__ ull pack2(float x, float y) {
    ull r; asm("mov.b64 %0, {%1, %2};" : "=l"(r) : "f"(x), "f"(y)); return r;
}
__device__ __forceinline__ void unpack2(ull v, float& x, float& y) {
    asm("mov.b64 {%0, %1}, %2;" : "=f"(x), "=f"(y) : "l"(v));
}
__device__ __forceinline__ void ffma2(ull& d, ull a, ull b) {
    asm("fma.rn.f32x2 %0, %1, %2, %0;" : "+l"(d) : "l"(a), "l"(b));
}
// low 16 bits = bf16(f0), high 16 = bf16(f1)
__device__ __forceinline__ uint32_t hi_pair(float f0, float f1) {
    uint32_t v; asm("cvt.rn.bf16x2.f32 %0, %1, %2;" : "=r"(v) : "f"(f1), "f"(f0)); return v;
}
__device__ __forceinline__ uint32_t lo_pair(float f0, float f1, uint32_t hp) {
    float h0 = __uint_as_float(hp << 16);
    float h1 = __uint_as_float(hp & 0xFFFF0000u);
    return hi_pair(f0 - h0, f1 - h1);
}

#define MMA(D, A, B0, B1)                                                  \
    asm volatile("mma.sync.aligned.m16n8k16.row.col.f32.bf16.bf16.f32 "    \
                 "{%0,%1,%2,%3},{%4,%5,%6,%7},{%8,%9},{%0,%1,%2,%3};"      \
                 : "+f"((D)[0]), "+f"((D)[1]), "+f"((D)[2]), "+f"((D)[3])  \
                 : "r"((A).x), "r"((A).y), "r"((A).z), "r"((A).w),         \
                   "r"(B0), "r"(B1))

// ---- prepass: W2 fp32 -> bf16 hi/lo fragments ----
__global__ void prep_kernel(const float* __restrict__ W2) {
    int j = blockIdx.x;          // 0..255 (output row)
    int kp = threadIdx.x;        // 0..127 (k-pair)
    int k = 2 * kp;
    float2 f = *reinterpret_cast<const float2*>(W2 + (size_t)j * 256 + k);
    uint32_t hv = hi_pair(f.x, f.y);
    uint32_t lv = lo_pair(f.x, f.y, hv);
    int J = j >> 4, r = j & 15, KT = k >> 4, q = k & 15;
    int a = ((r >> 3) & 1) | ((q >> 3) << 1);
    int lane = ((r & 7) << 2) | ((q & 7) >> 1);
    int idx = ((((J * 16 + KT) * 32 + lane) << 2) | a);
    reinterpret_cast<uint32_t*>(WFhi4)[idx] = hv;
    reinterpret_cast<uint32_t*>(WFlo4)[idx] = lv;
}

// ---- smem layout (bytes) ----
#define OFF_BFH  0        // 32768: h1 hi B-fragments [mt8][kt16][lane32][r2] u32
#define OFF_BFL  32768    // 32768
#define OFF_W1J  65536    // 6144: [c][k] f32, k pair-contiguous
#define OFF_B1   71680    // 1024
#define OFF_XP   72704    // 3072: ull XP[c*64+m] packed broadcast inputs
#define OFF_RED  75776    // 2048: [warp8][m64] f32
#define SMEM_TOT 77824

__global__ __launch_bounds__(THREADS, 1)
void net_kernel(const float* __restrict__ X,      // [8192][96][4]
                const float* __restrict__ TN,     // [8192][96]
                const float* __restrict__ DN,     // [8192][96]
                const float* __restrict__ A0,     // [8192]
                const float* __restrict__ S0,     // [8192]
                const float* __restrict__ LAM,
                const float* __restrict__ BUD,
                const float* __restrict__ W1,     // [256][6]
                const float* __restrict__ B1,     // [256]
                const float* __restrict__ B2,     // [256]
                const float* __restrict__ W3,     // [256]
                const float* __restrict__ B3,     // [1]
                float* __restrict__ OUT)          // [8192][96]
{
    extern __shared__ __align__(16) char smem[];
    uint32_t* BFh = reinterpret_cast<uint32_t*>(smem + OFF_BFH);
    uint32_t* BFl = reinterpret_cast<uint32_t*>(smem + OFF_BFL);
    float*    W1J = reinterpret_cast<float*>(smem + OFF_W1J);
    float*    B1s = reinterpret_cast<float*>(smem + OFF_B1);
    ull*      XP  = reinterpret_cast<ull*>(smem + OFF_XP);
    float*    RED = reinterpret_cast<float*>(smem + OFF_RED);

    const int tid  = threadIdx.x;
    const int w    = tid >> 5;
    const int lane = tid & 31;
    const int g    = lane >> 2;      // row-group within fragment
    const int q4   = lane & 3;       // col-group within fragment
    const int base = blockIdx.x * MT;

    // stage W1 transposed [c][k] and B1
    for (int i = tid; i < 6 * 256; i += THREADS) {
        int c = i >> 8, k = i & 255;
        W1J[c * 256 + k] = W1[k * 6 + c];
    }
    for (int i = tid; i < 256; i += THREADS) B1s[i] = B1[i];

    const float lam = LAM[0], bud = BUD[0];
    const float budH     = __fdiv_rn(bud, 96.0f);
    const float per_step = lam * 2.0f + budH;
    const float b3v = B3[0];

    // per-thread epilogue constants: j = w*32 + jt*16 + g + 8*h
    float b2r[2][2], w3r[2][2];
    #pragma unroll
    for (int jt = 0; jt < 2; jt++)
        #pragma unroll
        for (int h = 0; h < 2; h++) {
            int j = w * 32 + jt * 16 + g + 8 * h;
            b2r[jt][h] = B2[j];
            w3r[jt][h] = W3[j];
        }

    // register state (threads 0..63) + initial XP staging
    float act = 0.f, st = 0.f, bgt = per_step, cumc = 0.f, adp = 0.f, Sv = 0.f;
    const float4* xrow = reinterpret_cast<const float4*>(X + (size_t)(base + (tid & 63)) * (NB * 4));
    if (tid < MT) {
        act = A0[base + tid];
        st  = S0[base + tid];
        float4 xv = xrow[0];
        XP[0 * 64 + tid] = pack2(xv.x, xv.x);
        XP[1 * 64 + tid] = pack2(xv.y, xv.y);
        XP[2 * 64 + tid] = pack2(xv.z, xv.z);
        XP[3 * 64 + tid] = pack2(xv.w, xv.w);
        XP[4 * 64 + tid] = pack2(act, act);
        XP[5 * 64 + tid] = pack2(st, st);
    }

    // A-fragment pointers: warp's J tiles are 2w and 2w+1
    const uint4* pA0h = WFhi4 + ((2 * w) * 16) * 32 + lane;
    const uint4* pA1h = pA0h + 16 * 32;
    const uint4* pA0l = WFlo4 + ((2 * w) * 16) * 32 + lane;
    const uint4* pA1l = pA0l + 16 * 32;

    __syncthreads();

    for (int t = 0; t < NB; t++) {
        // ======== layer 1: produce h1 hi/lo directly as B-fragments ========
        #pragma unroll 1
        for (int kk = 0; kk < 2; kk++) {
            const int kt = w * 2 + kk;
            const int k0 = kt * 16 + q4 * 2;     // r=0 k-pair
            const int k1 = k0 + 8;               // r=1 k-pair
            ull c0[7], c1[7];
            #pragma unroll
            for (int d = 0; d < 6; d++) {
                c0[d] = *reinterpret_cast<const ull*>(&W1J[d * 256 + k0]);
                c1[d] = *reinterpret_cast<const ull*>(&W1J[d * 256 + k1]);
            }
            c0[6] = *reinterpret_cast<const ull*>(&B1s[k0]);
            c1[6] = *reinterpret_cast<const ull*>(&B1s[k1]);
            #pragma unroll
            for (int mt = 0; mt < 8; mt++) {
                const int m = mt * 8 + g;
                ull x0 = XP[m],        x1 = XP[64 + m],  x2 = XP[128 + m];
                ull x3 = XP[192 + m],  x4 = XP[256 + m], x5 = XP[320 + m];
                // r = 0
                ull s = c0[6];
                ffma2(s, c0[0], x0); ffma2(s, c0[1], x1); ffma2(s, c0[2], x2);
                ffma2(s, c0[3], x3); ffma2(s, c0[4], x4); ffma2(s, c0[5], x5);
                float s0, s1; unpack2(s, s0, s1);
                s0 = fmaxf(s0, 0.0f); s1 = fmaxf(s1, 0.0f);
                uint32_t hv0 = hi_pair(s0, s1);
                uint32_t lv0 = lo_pair(s0, s1, hv0);
                // r = 1
                s = c1[6];
                ffma2(s, c1[0], x0); ffma2(s, c1[1], x1); ffma2(s, c1[2], x2);
                ffma2(s, c1[3], x3); ffma2(s, c1[4], x4); ffma2(s, c1[5], x5);
                unpack2(s, s0, s1);
                s0 = fmaxf(s0, 0.0f); s1 = fmaxf(s1, 0.0f);
                uint32_t hv1 = hi_pair(s0, s1);
                uint32_t lv1 = lo_pair(s0, s1, hv1);

                const int fi = ((mt * 16 + kt) * 32 + lane) * 2;
                *reinterpret_cast<ull*>(&BFh[fi]) = (ull)hv0 | ((ull)hv1 << 32);
                *reinterpret_cast<ull*>(&BFl[fi]) = (ull)lv0 | ((ull)lv1 << 32);
            }
        }
        __syncthreads();

        // ======== GEMM: 3 bf16 terms, D[jt2][mt8] f32 ========
        float d[16][4];
        #pragma unroll
        for (int i = 0; i < 16; i++) { d[i][0] = 0.f; d[i][1] = 0.f; d[i][2] = 0.f; d[i][3] = 0.f; }

        #pragma unroll 4
        for (int kt = 0; kt < 16; kt++) {
            uint4 ah0 = pA0h[kt * 32];
            uint4 ah1 = pA1h[kt * 32];
            uint4 al0 = pA0l[kt * 32];
            uint4 al1 = pA1l[kt * 32];
            #pragma unroll
            for (int mt = 0; mt < 8; mt++) {
                const int fi = ((mt * 16 + kt) * 32 + lane) * 2;
                uint32_t bh0 = BFh[fi], bh1 = BFh[fi + 1];
                uint32_t bl0 = BFl[fi], bl1 = BFl[fi + 1];
                MMA(d[mt],     ah0, bh0, bh1);
                MMA(d[8 + mt], ah1, bh0, bh1);
                MMA(d[mt],     ah0, bl0, bl1);
                MMA(d[8 + mt], ah1, bl0, bl1);
                MMA(d[mt],     al0, bh0, bh1);
                MMA(d[8 + mt], al1, bh0, bh1);
            }
        }

        // ======== epilogue: cm[m] = sum_j w3[j]*relu(D+b2) ========
        float cm[16];
        #pragma unroll
        for (int i = 0; i < 16; i++) cm[i] = 0.0f;
        #pragma unroll
        for (int jt = 0; jt < 2; jt++) {
            #pragma unroll
            for (int mt = 0; mt < 8; mt++) {
                const float* dd = d[jt * 8 + mt];
                cm[2 * mt]     += w3r[jt][0] * fmaxf(dd[0] + b2r[jt][0], 0.0f)
                                + w3r[jt][1] * fmaxf(dd[2] + b2r[jt][1], 0.0f);
                cm[2 * mt + 1] += w3r[jt][0] * fmaxf(dd[1] + b2r[jt][0], 0.0f)
                                + w3r[jt][1] * fmaxf(dd[3] + b2r[jt][1], 0.0f);
            }
        }
        #pragma unroll
        for (int off = 4; off <= 16; off <<= 1) {
            #pragma unroll
            for (int i = 0; i < 16; i++)
                cm[i] += __shfl_xor_sync(0xFFFFFFFFu, cm[i], off);
        }
        if (lane < 4) {
            #pragma unroll
            for (int mt = 0; mt < 8; mt++)
                *reinterpret_cast<float2*>(&RED[w * 64 + mt * 8 + lane * 2]) =
                    make_float2(cm[2 * mt], cm[2 * mt + 1]);
        }
        __syncthreads();

        // ======== scalar recurrence (threads 0..63, state in regs) ========
        if (tid < MT) {
            const int m = tid;
            float a_ml = b3v;
            #pragma unroll
            for (int ww = 0; ww < 8; ww++) a_ml += RED[ww * 64 + m];
            a_ml = fmaxf(a_ml, 0.0f);

            float demand = reinterpret_cast<const float*>(XP)[m * 2]; // low word of XP[0][m]
            float a_prior = fminf(__fdiv_rn(fmaxf(st + demand, 0.0f), 0.8f), 10.0f);

            int n = 95 - t;
            float p = (n <= 63) ? __uint_as_float((unsigned)(127 - 2 * n) << 23) : 0.0f;
            float Gamma = 2.0f + 0.5f * (1.0f - p);

            float sgn = (a_ml < a_prior) ? 1.0f : -1.0f;
            float a_out = a_ml +
                fmaxf(fabsf(a_ml - a_prior) - __fdiv_rn(bgt, Gamma), 0.0f) * sgn;

            float noise  = TN[(size_t)(base + m) * NB + t];
            float noise2 = DN[(size_t)(base + m) * NB + t];
            float ns = fminf(fmaxf(st * (1.0f - noise2) + demand
                                   - (0.8f + noise) * a_out, 0.0f), 15.0f);
            float c_cost = 0.1f * ns * ns + ns + 2.0f;

            float ad_new = fabsf(a_out - a_prior);
            float Snew = 0.25f * Sv + ad_new;
            float cum_d = 2.0f * ad_new + 0.375f * Sv;
            float c_prior = fmaxf(2.0f, c_cost - cum_d);
            float cum_c_new = cumc + (1.0f + lam) * c_prior - c_cost;
            float cum_d_g = 0.5f * Snew * (1.0f - p);

            float bgt_if = fmaxf(fmaxf(bgt + per_step - ad_new * Gamma, 0.0f),
                                 cum_c_new - cum_d_g + lam * 2.0f + budH * (float)(t + 2));
            float bgt_else = fmaxf(bgt + per_step - adp * Gamma, 0.0f);

            bool last = (t == NB - 1);
            bgt  = last ? bgt_else : bgt_if;
            cumc = last ? cumc : cum_c_new;
            adp  = ad_new;
            act  = a_out;
            st   = ns;
            Sv   = Snew;
            OUT[(size_t)(base + m) * NB + t] = a_out;

            // stage XP for t+1
            int tn = (t + 1 < NB) ? t + 1 : NB - 1;
            float4 xv = xrow[tn];
            XP[m]       = pack2(xv.x, xv.x);
            XP[64 + m]  = pack2(xv.y, xv.y);
            XP[128 + m] = pack2(xv.z, xv.z);
            XP[192 + m] = pack2(xv.w, xv.w);
            XP[256 + m] = pack2(act, act);
            XP[320 + m] = pack2(st, st);
        }
        __syncthreads();
    }
}

extern "C" void kernel_launch(void* const* d_in, const int* in_sizes, int n_in,
                              void* d_out, int out_size) {
    (void)in_sizes; (void)n_in; (void)out_size;
    cudaFuncSetAttribute(net_kernel, cudaFuncAttributeMaxDynamicSharedMemorySize, SMEM_TOT);
    prep_kernel<<<256, 128>>>((const float*)d_in[9]);   // W2
    net_kernel<<<NCTA, THREADS, SMEM_TOT>>>(
        (const float*)d_in[0],   // policy_in_c
        (const float*)d_in[1],   // trans_noise
        (const float*)d_in[2],   // demand_noise
        (const float*)d_in[3],   // action_pre
        (const float*)d_in[4],   // state_pre
        (const float*)d_in[5],   // Lambda
        (const float*)d_in[6],   // Budget
        (const float*)d_in[7],   // W1
        (const float*)d_in[8],   // b1
        (const float*)d_in[10],  // b2
        (const float*)d_in[11],  // W3
        (const float*)d_in[12],  // b3
        (float*)d_out);
}

// round 10
// speedup vs baseline: 5.6217x; 1.0284x over previous
#include <cuda_runtime.h>
#include <cstdint>

#define NB      96
#define MT      32
#define THREADS 256
#define NCTA    256

typedef unsigned long long ull;

// W2 fragments, fragment-linear: [J(16)][KT(16)][lane(32)] x uint4(a0..a3)
__device__ uint4 WFhi4[16 * 16 * 32];
__device__ uint4 WFlo4[16 * 16 * 32];

// ---- helpers ----
__device__ __forceinline__ ull pack2(float x, float y) {
    ull r; asm("mov.b64 %0, {%1, %2};" : "=l"(r) : "f"(x), "f"(y)); return r;
}
__device__ __forceinline__ void unpack2(ull v, float& x, float& y) {
    asm("mov.b64 {%0, %1}, %2;" : "=f"(x), "=f"(y) : "l"(v));
}
__device__ __forceinline__ void ffma2(ull& d, ull a, ull b) {
    asm("fma.rn.f32x2 %0, %1, %2, %0;" : "+l"(d) : "l"(a), "l"(b));
}
// low 16 bits = bf16(f0), high 16 = bf16(f1)
__device__ __forceinline__ uint32_t hi_pair(float f0, float f1) {
    uint32_t v; asm("cvt.rn.bf16x2.f32 %0, %1, %2;" : "=r"(v) : "f"(f1), "f"(f0)); return v;
}
__device__ __forceinline__ uint32_t lo_pair(float f0, float f1, uint32_t hp) {
    float h0 = __uint_as_float(hp << 16);
    float h1 = __uint_as_float(hp & 0xFFFF0000u);
    return hi_pair(f0 - h0, f1 - h1);
}

#define MMA(D, A, B0, B1)                                                  \
    asm volatile("mma.sync.aligned.m16n8k16.row.col.f32.bf16.bf16.f32 "    \
                 "{%0,%1,%2,%3},{%4,%5,%6,%7},{%8,%9},{%0,%1,%2,%3};"      \
                 : "+f"((D)[0]), "+f"((D)[1]), "+f"((D)[2]), "+f"((D)[3])  \
                 : "r"((A).x), "r"((A).y), "r"((A).z), "r"((A).w),         \
                   "r"(B0), "r"(B1))

// ---- prepass: W2 fp32 -> bf16 hi/lo fragments ----
__global__ void prep_kernel(const float* __restrict__ W2) {
    int j = blockIdx.x;          // 0..255 (output row)
    int kp = threadIdx.x;        // 0..127 (k-pair)
    int k = 2 * kp;
    float2 f = *reinterpret_cast<const float2*>(W2 + (size_t)j * 256 + k);
    uint32_t hv = hi_pair(f.x, f.y);
    uint32_t lv = lo_pair(f.x, f.y, hv);
    int J = j >> 4, r = j & 15, KT = k >> 4, q = k & 15;
    int a = ((r >> 3) & 1) | ((q >> 3) << 1);
    int lane = ((r & 7) << 2) | ((q & 7) >> 1);
    int idx = ((((J * 16 + KT) * 32 + lane) << 2) | a);
    reinterpret_cast<uint32_t*>(WFhi4)[idx] = hv;
    reinterpret_cast<uint32_t*>(WFlo4)[idx] = lv;
}

// ---- smem layout (bytes) ----
#define OFF_BFH  0        // 16384: h1 hi B-fragments [mt4][kt16][lane32][r2] u32
#define OFF_BFL  16384    // 16384
#define OFF_W1J  32768    // 6144: [c][k] f32, k pair-contiguous
#define OFF_B1   38912    // 1024
#define OFF_XP   39936    // 1536: ull XP[c*32+m] packed broadcast inputs
#define OFF_RED  41472    // 1024: [warp8][m32] f32
#define SMEM_TOT 42496

__global__ __launch_bounds__(THREADS, 2)
void net_kernel(const float* __restrict__ X,      // [8192][96][4]
                const float* __restrict__ TN,     // [8192][96]
                const float* __restrict__ DN,     // [8192][96]
                const float* __restrict__ A0,     // [8192]
                const float* __restrict__ S0,     // [8192]
                const float* __restrict__ LAM,
                const float* __restrict__ BUD,
                const float* __restrict__ W1,     // [256][6]
                const float* __restrict__ B1,     // [256]
                const float* __restrict__ B2,     // [256]
                const float* __restrict__ W3,     // [256]
                const float* __restrict__ B3,     // [1]
                float* __restrict__ OUT)          // [8192][96]
{
    extern __shared__ __align__(16) char smem[];
    uint32_t* BFh = reinterpret_cast<uint32_t*>(smem + OFF_BFH);
    uint32_t* BFl = reinterpret_cast<uint32_t*>(smem + OFF_BFL);
    float*    W1J = reinterpret_cast<float*>(smem + OFF_W1J);
    float*    B1s = reinterpret_cast<float*>(smem + OFF_B1);
    ull*      XP  = reinterpret_cast<ull*>(smem + OFF_XP);
    float*    RED = reinterpret_cast<float*>(smem + OFF_RED);

    const int tid  = threadIdx.x;
    const int w    = tid >> 5;
    const int lane = tid & 31;
    const int g    = lane >> 2;      // row-group within fragment
    const int q4   = lane & 3;       // col-group within fragment
    const int base = blockIdx.x * MT;

    // stage W1 transposed [c][k] and B1
    for (int i = tid; i < 6 * 256; i += THREADS) {
        int c = i >> 8, k = i & 255;
        W1J[c * 256 + k] = W1[k * 6 + c];
    }
    for (int i = tid; i < 256; i += THREADS) B1s[i] = B1[i];

    const float lam = LAM[0], bud = BUD[0];
    const float budH     = __fdiv_rn(bud, 96.0f);
    const float per_step = lam * 2.0f + budH;
    const float b3v = B3[0];

    // per-thread epilogue constants: j = w*32 + jt*16 + g + 8*h
    float b2r[2][2], w3r[2][2];
    #pragma unroll
    for (int jt = 0; jt < 2; jt++)
        #pragma unroll
        for (int h = 0; h < 2; h++) {
            int j = w * 32 + jt * 16 + g + 8 * h;
            b2r[jt][h] = B2[j];
            w3r[jt][h] = W3[j];
        }

    // register state (threads 0..31) + initial XP staging
    float act = 0.f, st = 0.f, bgt = per_step, cumc = 0.f, adp = 0.f, Sv = 0.f;
    const float4* xrow = reinterpret_cast<const float4*>(X + (size_t)(base + (tid & 31)) * (NB * 4));
    if (tid < MT) {
        act = A0[base + tid];
        st  = S0[base + tid];
        float4 xv = xrow[0];
        XP[0 * 32 + tid] = pack2(xv.x, xv.x);
        XP[1 * 32 + tid] = pack2(xv.y, xv.y);
        XP[2 * 32 + tid] = pack2(xv.z, xv.z);
        XP[3 * 32 + tid] = pack2(xv.w, xv.w);
        XP[4 * 32 + tid] = pack2(act, act);
        XP[5 * 32 + tid] = pack2(st, st);
    }

    // A-fragment pointers: warp's J tiles are 2w and 2w+1
    const uint4* pA0h = WFhi4 + ((2 * w) * 16) * 32 + lane;
    const uint4* pA1h = pA0h + 16 * 32;
    const uint4* pA0l = WFlo4 + ((2 * w) * 16) * 32 + lane;
    const uint4* pA1l = pA0l + 16 * 32;

    __syncthreads();

    for (int t = 0; t < NB; t++) {
        // ======== layer 1: produce h1 hi/lo directly as B-fragments ========
        #pragma unroll 1
        for (int kk = 0; kk < 2; kk++) {
            const int kt = w * 2 + kk;
            const int k0 = kt * 16 + q4 * 2;     // r=0 k-pair
            const int k1 = k0 + 8;               // r=1 k-pair
            ull c0[7], c1[7];
            #pragma unroll
            for (int d = 0; d < 6; d++) {
                c0[d] = *reinterpret_cast<const ull*>(&W1J[d * 256 + k0]);
                c1[d] = *reinterpret_cast<const ull*>(&W1J[d * 256 + k1]);
            }
            c0[6] = *reinterpret_cast<const ull*>(&B1s[k0]);
            c1[6] = *reinterpret_cast<const ull*>(&B1s[k1]);
            #pragma unroll
            for (int mt = 0; mt < 4; mt++) {
                const int m = mt * 8 + g;
                ull x0 = XP[m],       x1 = XP[32 + m],  x2 = XP[64 + m];
                ull x3 = XP[96 + m],  x4 = XP[128 + m], x5 = XP[160 + m];
                // r = 0
                ull s = c0[6];
                ffma2(s, c0[0], x0); ffma2(s, c0[1], x1); ffma2(s, c0[2], x2);
                ffma2(s, c0[3], x3); ffma2(s, c0[4], x4); ffma2(s, c0[5], x5);
                float s0, s1; unpack2(s, s0, s1);
                s0 = fmaxf(s0, 0.0f); s1 = fmaxf(s1, 0.0f);
                uint32_t hv0 = hi_pair(s0, s1);
                uint32_t lv0 = lo_pair(s0, s1, hv0);
                // r = 1
                s = c1[6];
                ffma2(s, c1[0], x0); ffma2(s, c1[1], x1); ffma2(s, c1[2], x2);
                ffma2(s, c1[3], x3); ffma2(s, c1[4], x4); ffma2(s, c1[5], x5);
                unpack2(s, s0, s1);
                s0 = fmaxf(s0, 0.0f); s1 = fmaxf(s1, 0.0f);
                uint32_t hv1 = hi_pair(s0, s1);
                uint32_t lv1 = lo_pair(s0, s1, hv1);

                const int fi = ((mt * 16 + kt) * 32 + lane) * 2;
                *reinterpret_cast<ull*>(&BFh[fi]) = (ull)hv0 | ((ull)hv1 << 32);
                *reinterpret_cast<ull*>(&BFl[fi]) = (ull)lv0 | ((ull)lv1 << 32);
            }
        }
        __syncthreads();

        // ======== GEMM: 3 bf16 terms, D[jt2][mt4] f32 ========
        float d[8][4];
        #pragma unroll
        for (int i = 0; i < 8; i++) { d[i][0] = 0.f; d[i][1] = 0.f; d[i][2] = 0.f; d[i][3] = 0.f; }

        #pragma unroll 2
        for (int kt = 0; kt < 16; kt++) {
            uint4 ah0 = pA0h[kt * 32];
            uint4 ah1 = pA1h[kt * 32];
            uint4 al0 = pA0l[kt * 32];
            uint4 al1 = pA1l[kt * 32];
            #pragma unroll
            for (int mt = 0; mt < 4; mt++) {
                const int fi = ((mt * 16 + kt) * 32 + lane) * 2;
                uint32_t bh0 = BFh[fi], bh1 = BFh[fi + 1];
                uint32_t bl0 = BFl[fi], bl1 = BFl[fi + 1];
                MMA(d[mt],     ah0, bh0, bh1);
                MMA(d[4 + mt], ah1, bh0, bh1);
                MMA(d[mt],     ah0, bl0, bl1);
                MMA(d[4 + mt], ah1, bl0, bl1);
                MMA(d[mt],     al0, bh0, bh1);
                MMA(d[4 + mt], al1, bh0, bh1);
            }
        }

        // ======== epilogue: cm[m] = sum_j w3[j]*relu(D+b2) ========
        float cm[8];
        #pragma unroll
        for (int i = 0; i < 8; i++) cm[i] = 0.0f;
        #pragma unroll
        for (int jt = 0; jt < 2; jt++) {
            #pragma unroll
            for (int mt = 0; mt < 4; mt++) {
                const float* dd = d[jt * 4 + mt];
                cm[2 * mt]     += w3r[jt][0] * fmaxf(dd[0] + b2r[jt][0], 0.0f)
                                + w3r[jt][1] * fmaxf(dd[2] + b2r[jt][1], 0.0f);
                cm[2 * mt + 1] += w3r[jt][0] * fmaxf(dd[1] + b2r[jt][0], 0.0f)
                                + w3r[jt][1] * fmaxf(dd[3] + b2r[jt][1], 0.0f);
            }
        }
        #pragma unroll
        for (int off = 4; off <= 16; off <<= 1) {
            #pragma unroll
            for (int i = 0; i < 8; i++)
                cm[i] += __shfl_xor_sync(0xFFFFFFFFu, cm[i], off);
        }
        if (lane < 4) {
            #pragma unroll
            for (int mt = 0; mt < 4; mt++)
                *reinterpret_cast<float2*>(&RED[w * 32 + mt * 8 + lane * 2]) =
                    make_float2(cm[2 * mt], cm[2 * mt + 1]);
        }
        __syncthreads();

        // ======== scalar recurrence (threads 0..31, state in regs) ========
        if (tid < MT) {
            const int m = tid;
            float a_ml = b3v;
            #pragma unroll
            for (int ww = 0; ww < 8; ww++) a_ml += RED[ww * 32 + m];
            a_ml = fmaxf(a_ml, 0.0f);

            float demand = reinterpret_cast<const float*>(XP)[m * 2]; // low word of XP[0][m]
            float a_prior = fminf(__fdiv_rn(fmaxf(st + demand, 0.0f), 0.8f), 10.0f);

            int n = 95 - t;
            float p = (n <= 63) ? __uint_as_float((unsigned)(127 - 2 * n) << 23) : 0.0f;
            float Gamma = 2.0f + 0.5f * (1.0f - p);

            float sgn = (a_ml < a_prior) ? 1.0f : -1.0f;
            float a_out = a_ml +
                fmaxf(fabsf(a_ml - a_prior) - __fdiv_rn(bgt, Gamma), 0.0f) * sgn;

            float noise  = TN[(size_t)(base + m) * NB + t];
            float noise2 = DN[(size_t)(base + m) * NB + t];
            float ns = fminf(fmaxf(st * (1.0f - noise2) + demand
                                   - (0.8f + noise) * a_out, 0.0f), 15.0f);
            float c_cost = 0.1f * ns * ns + ns + 2.0f;

            float ad_new = fabsf(a_out - a_prior);
            float Snew = 0.25f * Sv + ad_new;
            float cum_d = 2.0f * ad_new + 0.375f * Sv;
            float c_prior = fmaxf(2.0f, c_cost - cum_d);
            float cum_c_new = cumc + (1.0f + lam) * c_prior - c_cost;
            float cum_d_g = 0.5f * Snew * (1.0f - p);

            float bgt_if = fmaxf(fmaxf(bgt + per_step - ad_new * Gamma, 0.0f),
                                 cum_c_new - cum_d_g + lam * 2.0f + budH * (float)(t + 2));
            float bgt_else = fmaxf(bgt + per_step - adp * Gamma, 0.0f);

            bool last = (t == NB - 1);
            bgt  = last ? bgt_else : bgt_if;
            cumc = last ? cumc : cum_c_new;
            adp  = ad_new;
            act  = a_out;
            st   = ns;
            Sv   = Snew;
            OUT[(size_t)(base + m) * NB + t] = a_out;

            // stage XP for t+1
            int tn = (t + 1 < NB) ? t + 1 : NB - 1;
            float4 xv = xrow[tn];
            XP[m]       = pack2(xv.x, xv.x);
            XP[32 + m]  = pack2(xv.y, xv.y);
            XP[64 + m]  = pack2(xv.z, xv.z);
            XP[96 + m]  = pack2(xv.w, xv.w);
            XP[128 + m] = pack2(act, act);
            XP[160 + m] = pack2(st, st);
        }
        __syncthreads();
    }
}

extern "C" void kernel_launch(void* const* d_in, const int* in_sizes, int n_in,
                              void* d_out, int out_size) {
    (void)in_sizes; (void)n_in; (void)out_size;
    cudaFuncSetAttribute(net_kernel, cudaFuncAttributeMaxDynamicSharedMemorySize, SMEM_TOT);
    prep_kernel<<<256, 128>>>((const float*)d_in[9]);   // W2
    net_kernel<<<NCTA, THREADS, SMEM_TOT>>>(
        (const float*)d_in[0],   // policy_in_c
        (const float*)d_in[1],   // trans_noise
        (const float*)d_in[2],   // demand_noise
        (const float*)d_in[3],   // action_pre
        (const float*)d_in[4],   // state_pre
        (const float*)d_in[5],   // Lambda
        (const float*)d_in[6],   // Budget
        (const float*)d_in[7],   // W1
        (const float*)d_in[8],   // b1
        (const float*)d_in[10],  // b2
        (const float*)d_in[11],  // W3
        (const float*)d_in[12],  // b3
        (float*)d_out);
}